// round 16
// baseline (speedup 1.0000x reference)
#include <cuda_runtime.h>
#include <cuda_bf16.h>
#include <cstdint>

// y = x * softplus(x@W1^T + b1) * sum_n((x@W2^T+b2)*(x@W3^T+b3))
// B=4, L=2048 -> T=8192 tokens, D=1024, N=16. A input is dead math.
//
// mma.sync.m16n8k16.bf16 (HMMA) + ldmatrix + 3-stage cp.async pipeline.
// Split precision: x=xh+xl, W1=wh+wl (bf16):
//   z = xh@wh^T + xl@wh^T + xh@wl^T   (xl@wl dropped, ~2^-18 rel)
// R11: MERGED single K-loop — per chunk load xh/xl/wh/wl once, issue all
// three MMA combos into one accumulator. 3x fewer barriers, 2.25x less L2
// traffic vs 3-pass. CTA 128x128, 256 thr, 3 stages x 64KB.

#define T_TOKENS 8192
#define DMODEL   1024
#define NSTATE   16

__device__ float          g_bc[T_TOKENS];
__device__ __nv_bfloat16  g_xh[T_TOKENS * DMODEL];
__device__ __nv_bfloat16  g_xl[T_TOKENS * DMODEL];
__device__ __nv_bfloat16  g_wh[DMODEL * DMODEL];
__device__ __nv_bfloat16  g_wl[DMODEL * DMODEL];

// ---------------------------------------------------------------------------
__device__ __forceinline__ uint32_t smem_u32(const void* p) {
    uint32_t a;
    asm("{ .reg .u64 t; cvta.to.shared.u64 t, %1; cvt.u32.u64 %0, t; }"
        : "=r"(a) : "l"(p));
    return a;
}

#define SW128(o) ((o) ^ (((o) >> 3) & 0x70))

#define CP_ASYNC16(dst, src) \
    asm volatile("cp.async.cg.shared.global [%0], [%1], 16;" \
                 :: "r"(dst), "l"(src) : "memory")
#define CP_COMMIT() asm volatile("cp.async.commit_group;" ::: "memory")
#define CP_WAIT1()  asm volatile("cp.async.wait_group 1;" ::: "memory")
#define CP_WAIT0()  asm volatile("cp.async.wait_group 0;" ::: "memory")

#define LDSM4(r, addr) \
    asm volatile("ldmatrix.sync.aligned.m8n8.x4.shared.b16 {%0,%1,%2,%3}, [%4];" \
        : "=r"((r)[0]), "=r"((r)[1]), "=r"((r)[2]), "=r"((r)[3]) : "r"(addr))

#define MMA16816(d, a, b0v, b1v) \
    asm volatile("mma.sync.aligned.m16n8k16.row.col.f32.bf16.bf16.f32 " \
        "{%0,%1,%2,%3}, {%4,%5,%6,%7}, {%8,%9}, {%0,%1,%2,%3};" \
        : "+f"((d)[0]), "+f"((d)[1]), "+f"((d)[2]), "+f"((d)[3]) \
        : "r"((a)[0]), "r"((a)[1]), "r"((a)[2]), "r"((a)[3]), \
          "r"(b0v), "r"(b1v))

__device__ __forceinline__ float softplus_f(float z) {
    return fmaxf(z, 0.f) + __logf(1.f + __expf(-fabsf(z)));
}

// ---------------------------------------------------------------------------
// Kernel A: fp32 -> (bf16 hi, bf16 lo) split (W1 only; x-split fused in B).
// ---------------------------------------------------------------------------
__global__ __launch_bounds__(256) void split_kernel(
    const float* __restrict__ src, __nv_bfloat16* __restrict__ hi,
    __nv_bfloat16* __restrict__ lo, int n4)
{
    int i = blockIdx.x * blockDim.x + threadIdx.x;
    if (i >= n4) return;
    float4 v = reinterpret_cast<const float4*>(src)[i];
    float f[4] = {v.x, v.y, v.z, v.w};
    __nv_bfloat16 h[4], l[4];
    #pragma unroll
    for (int j = 0; j < 4; j++) {
        h[j] = __float2bfloat16(f[j]);
        l[j] = __float2bfloat16(f[j] - __bfloat162float(h[j]));
    }
    ushort4 ho, lov;
    ho.x = *(unsigned short*)&h[0]; ho.y = *(unsigned short*)&h[1];
    ho.z = *(unsigned short*)&h[2]; ho.w = *(unsigned short*)&h[3];
    lov.x = *(unsigned short*)&l[0]; lov.y = *(unsigned short*)&l[1];
    lov.z = *(unsigned short*)&l[2]; lov.w = *(unsigned short*)&l[3];
    reinterpret_cast<ushort4*>(hi)[i] = ho;
    reinterpret_cast<ushort4*>(lo)[i] = lov;
}

// ---------------------------------------------------------------------------
// Kernel B: bc[t] = sum_n (x[t]·W2[n]+b2[n])*(x[t]·W3[n]+b3[n]); also emits
// the bf16 hi/lo split of x. R11: 32 tokens/block, grid 256 (>148 SMs).
// ---------------------------------------------------------------------------
__global__ __launch_bounds__(256) void bc_split_kernel(
    const float* __restrict__ x,
    const float* __restrict__ W2, const float* __restrict__ b2,
    const float* __restrict__ W3, const float* __restrict__ b3)
{
    const int TPB = 32, KC = 32;
    __shared__ float xs[TPB][36];
    __shared__ float w2s[NSTATE][36];
    __shared__ float w3s[NSTATE][36];
    __shared__ float red[TPB][17];

    int tid = threadIdx.x;
    int n   = tid & 15;
    int gid = tid >> 4;               // 0..15, 2 tokens each
    int rowBase = blockIdx.x * TPB;

    float accB[2] = {0.f, 0.f};
    float accC[2] = {0.f, 0.f};

    for (int k0 = 0; k0 < DMODEL; k0 += KC) {
        {   // x chunk: 32 rows x 32 k = 256 float4, 1 per thread
            int row = tid >> 3, q = tid & 7;
            size_t gofs = (size_t)(rowBase + row) * DMODEL + k0 + q * 4;
            float4 v = *reinterpret_cast<const float4*>(x + gofs);
            xs[row][q*4+0] = v.x; xs[row][q*4+1] = v.y;
            xs[row][q*4+2] = v.z; xs[row][q*4+3] = v.w;
            float f4[4] = {v.x, v.y, v.z, v.w};
            __nv_bfloat16 h[4], l[4];
            #pragma unroll
            for (int e = 0; e < 4; e++) {
                h[e] = __float2bfloat16(f4[e]);
                l[e] = __float2bfloat16(f4[e] - __bfloat162float(h[e]));
            }
            ushort4 ho, lov;
            ho.x = *(unsigned short*)&h[0]; ho.y = *(unsigned short*)&h[1];
            ho.z = *(unsigned short*)&h[2]; ho.w = *(unsigned short*)&h[3];
            lov.x = *(unsigned short*)&l[0]; lov.y = *(unsigned short*)&l[1];
            lov.z = *(unsigned short*)&l[2]; lov.w = *(unsigned short*)&l[3];
            *reinterpret_cast<ushort4*>(g_xh + gofs) = ho;
            *reinterpret_cast<ushort4*>(g_xl + gofs) = lov;
        }
        {   // W2/W3 chunk: 16 x 32 each = 128 float4 each
            int f = tid & 127, row = f >> 3, q = f & 7;
            const float* src = (tid < 128) ? W2 : W3;
            float4 v = *reinterpret_cast<const float4*>(
                src + (size_t)row * DMODEL + k0 + q * 4);
            float (*dst)[36] = (tid < 128) ? w2s : w3s;
            dst[row][q*4+0] = v.x; dst[row][q*4+1] = v.y;
            dst[row][q*4+2] = v.z; dst[row][q*4+3] = v.w;
        }
        __syncthreads();

        #pragma unroll 8
        for (int kk = 0; kk < KC; kk++) {
            float w2 = w2s[n][kk], w3 = w3s[n][kk];
            #pragma unroll
            for (int t = 0; t < 2; t++) {
                float xv = xs[gid*2 + t][kk];
                accB[t] = fmaf(xv, w2, accB[t]);
                accC[t] = fmaf(xv, w3, accC[t]);
            }
        }
        __syncthreads();
    }

    float bb = b2[n], bb3 = b3[n];
    #pragma unroll
    for (int t = 0; t < 2; t++)
        red[gid*2 + t][n] = (accB[t] + bb) * (accC[t] + bb3);
    __syncthreads();

    if (tid < TPB) {
        float s = 0.f;
        #pragma unroll
        for (int nn = 0; nn < NSTATE; nn++) s += red[tid][nn];
        g_bc[rowBase + tid] = s;
    }
}

// ---------------------------------------------------------------------------
// Kernel C: merged-pass mma.sync bf16 GEMM + fused epilogue.
// CTA 128x128, 256 threads = 8 warps, warp tile 64x32.
// 16 K-chunks of 64; per chunk: 4 sub-tiles (xh,xl,wh,wl) loaded once,
// 3 MMA combos (ah*bh + al*bh + ah*bl) into one accumulator.
// 3-stage cp.async pipeline, stage = 64KB (AH|AL|BH|BL 16KB each).
// ---------------------------------------------------------------------------
#define NCHUNKS 16
#define NSTAGES 3
#define SUB_B   16384                       // 128 rows x 128B
#define STAGE_B (4 * SUB_B)                 // 64 KB
#define SMEM_TOTAL (NSTAGES * STAGE_B)      // 192 KB

__global__ __launch_bounds__(256) void mma_kernel(
    const float* __restrict__ x,
    const float* __restrict__ b1,
    float* __restrict__ y)
{
    extern __shared__ char smem[];
    const uint32_t sbase = smem_u32(smem);
    const int tid  = threadIdx.x;
    const int wid  = tid >> 5;
    const int lane = tid & 31;

    const int rowBase = blockIdx.y * 128;
    const int colBase = blockIdx.x * 128;

    const int wm = wid & 1;           // M half (64 rows)
    const int wn = wid >> 1;          // N quarter (32 cols)

    const __nv_bfloat16* pAH = g_xh + (size_t)rowBase * DMODEL;
    const __nv_bfloat16* pAL = g_xl + (size_t)rowBase * DMODEL;
    const __nv_bfloat16* pBH = g_wh + (size_t)colBase * DMODEL;
    const __nv_bfloat16* pBL = g_wl + (size_t)colBase * DMODEL;

    // ldmatrix per-lane coords (validated fragment algebra)
    const int a_row  = (lane & 7) + ((lane >> 3) & 1) * 8;       // 0..15
    const int a_byte = (lane >> 4) * 16;                          // k-half
    const int axor   = (a_row & 7) << 4;
    const int b_row  = ((lane >> 4) & 1) * 8 + (lane & 7);        // n within 16
    const int b_byte = ((lane >> 3) & 1) * 16;                    // k-half
    const int bxor   = (b_row & 7) << 4;

    float acc[4][4][4];
    #pragma unroll
    for (int mi = 0; mi < 4; mi++)
        #pragma unroll
        for (int ni = 0; ni < 4; ni++)
            #pragma unroll
            for (int r = 0; r < 4; r++) acc[mi][ni][r] = 0.f;

    // cp.async: 4096 uint4 per chunk / 256 threads = 16 each.
    // u in [0,16): matrix = u>>2 (0:AH 1:AL 2:BH 3:BL), idx = tid + (u&3)*256,
    // row = idx>>3 (0..127), q = idx&7.
    const int cp_row = tid >> 3;      // 0..31
    const int cp_q   = tid & 7;

    const __nv_bfloat16* mats[4] = {pAH, pAL, pBH, pBL};

    // prologue: issue chunks 0 and 1
    #pragma unroll
    for (int gg = 0; gg < 2; gg++) {
        int kc = gg << 6;
        uint32_t st = sbase + (uint32_t)gg * STAGE_B;
        #pragma unroll
        for (int m = 0; m < 4; m++) {
            const __nv_bfloat16* pm = mats[m];
            uint32_t mb = st + (uint32_t)m * SUB_B;
            #pragma unroll
            for (int v = 0; v < 4; v++) {
                int row = cp_row + v * 32;
                CP_ASYNC16(mb + SW128(row * 128 + cp_q * 16),
                           pm + (size_t)row * DMODEL + kc + cp_q * 8);
            }
        }
        CP_COMMIT();
    }

    #pragma unroll 1
    for (int g = 0; g < NCHUNKS; g++) {
        if (g < NCHUNKS - 1) { CP_WAIT1(); } else { CP_WAIT0(); }
        __syncthreads();

        // issue chunk g+2 into stage (g+2)%NSTAGES
        if (g + 2 < NCHUNKS) {
            int kc = (g + 2) << 6;
            uint32_t st = sbase + (uint32_t)((g + 2) % NSTAGES) * STAGE_B;
            #pragma unroll
            for (int m = 0; m < 4; m++) {
                const __nv_bfloat16* pm = mats[m];
                uint32_t mb = st + (uint32_t)m * SUB_B;
                #pragma unroll
                for (int v = 0; v < 4; v++) {
                    int row = cp_row + v * 32;
                    CP_ASYNC16(mb + SW128(row * 128 + cp_q * 16),
                               pm + (size_t)row * DMODEL + kc + cp_q * 8);
                }
            }
            CP_COMMIT();
        }

        const uint32_t st = sbase + (uint32_t)(g % NSTAGES) * STAGE_B;
        const uint32_t AH = st;
        const uint32_t AL = st + SUB_B;
        const uint32_t BH = st + 2 * SUB_B;
        const uint32_t BL = st + 3 * SUB_B;

        #pragma unroll
        for (int s = 0; s < 4; s++) {
            const int kb = s * 32;                 // 16 bf16 = 32B per kstep
            uint32_t ah[4][4], al[4][4], bh[2][4], bl[2][4];
            #pragma unroll
            for (int mi = 0; mi < 4; mi++) {
                uint32_t ro = (uint32_t)((wm * 64 + mi * 16 + a_row) * 128)
                            + (uint32_t)((kb + a_byte) ^ axor);
                LDSM4(ah[mi], AH + ro);
                LDSM4(al[mi], AL + ro);
            }
            #pragma unroll
            for (int bt = 0; bt < 2; bt++) {
                uint32_t ro = (uint32_t)((wn * 32 + bt * 16 + b_row) * 128)
                            + (uint32_t)((kb + b_byte) ^ bxor);
                LDSM4(bh[bt], BH + ro);
                LDSM4(bl[bt], BL + ro);
            }
            #pragma unroll
            for (int mi = 0; mi < 4; mi++) {
                #pragma unroll
                for (int ni = 0; ni < 4; ni++) {
                    const int bq = ni >> 1;
                    const int o  = (ni & 1) * 2;
                    MMA16816(acc[mi][ni], ah[mi], bh[bq][o], bh[bq][o + 1]);
                    MMA16816(acc[mi][ni], al[mi], bh[bq][o], bh[bq][o + 1]);
                    MMA16816(acc[mi][ni], ah[mi], bl[bq][o], bl[bq][o + 1]);
                }
            }
        }
    }

    // Epilogue: y = x * softplus(z + b1) * bc
    const int gq = lane >> 2;    // row-in-8 group
    const int tq = lane & 3;     // col pair
    #pragma unroll
    for (int mi = 0; mi < 4; mi++) {
        int r0 = rowBase + wm * 64 + mi * 16 + gq;
        int r1 = r0 + 8;
        float bc0 = g_bc[r0], bc1 = g_bc[r1];
        const float* x0 = x + (size_t)r0 * DMODEL;
        const float* x1 = x + (size_t)r1 * DMODEL;
        float* y0 = y + (size_t)r0 * DMODEL;
        float* y1 = y + (size_t)r1 * DMODEL;
        #pragma unroll
        for (int ni = 0; ni < 4; ni++) {
            int c = colBase + wn * 32 + ni * 8 + tq * 2;
            float2 bv  = *reinterpret_cast<const float2*>(b1 + c);
            float2 xv0 = *reinterpret_cast<const float2*>(x0 + c);
            float2 xv1 = *reinterpret_cast<const float2*>(x1 + c);
            float2 o0, o1;
            o0.x = xv0.x * softplus_f(acc[mi][ni][0] + bv.x) * bc0;
            o0.y = xv0.y * softplus_f(acc[mi][ni][1] + bv.y) * bc0;
            o1.x = xv1.x * softplus_f(acc[mi][ni][2] + bv.x) * bc1;
            o1.y = xv1.y * softplus_f(acc[mi][ni][3] + bv.y) * bc1;
            *reinterpret_cast<float2*>(y0 + c) = o0;
            *reinterpret_cast<float2*>(y1 + c) = o1;
        }
    }
}

// ---------------------------------------------------------------------------
extern "C" void kernel_launch(void* const* d_in, const int* in_sizes, int n_in,
                              void* d_out, int out_size)
{
    const float* x  = (const float*)d_in[0];
    const float* W1 = (const float*)d_in[1];
    const float* b1 = (const float*)d_in[2];
    const float* W2 = (const float*)d_in[3];
    const float* b2 = (const float*)d_in[4];
    const float* W3 = (const float*)d_in[5];
    const float* b3 = (const float*)d_in[6];
    float* y = (float*)d_out;

    __nv_bfloat16 *wh, *wl;
    cudaGetSymbolAddress((void**)&wh, g_wh);
    cudaGetSymbolAddress((void**)&wl, g_wl);

    int nw4 = DMODEL * DMODEL / 4;
    split_kernel<<<nw4 / 256, 256>>>(W1, wh, wl, nw4);
    bc_split_kernel<<<T_TOKENS / 32, 256>>>(x, W2, b2, W3, b3);

    cudaFuncSetAttribute(mma_kernel, cudaFuncAttributeMaxDynamicSharedMemorySize,
                         SMEM_TOTAL);
    mma_kernel<<<dim3(DMODEL / 128, T_TOKENS / 128), 256, SMEM_TOTAL>>>(x, b1, y);
}

// round 17
// speedup vs baseline: 1.1322x; 1.1322x over previous
#include <cuda_runtime.h>
#include <cuda_bf16.h>
#include <cstdint>

// y = x * softplus(x@W1^T + b1) * sum_n((x@W2^T+b2)*(x@W3^T+b3))
// B=4, L=2048 -> T=8192 tokens, D=1024, N=16. A input is dead math.
//
// mma.sync.m16n8k16.bf16 (HMMA) + ldmatrix + cp.async.
// Split precision: x=xh+xl, W1=wh+wl (bf16):
//   z = xh@wh^T + xl@wh^T + xh@wl^T   (xl@wl dropped, ~2^-18 rel)
// R16: merged single K-loop (load xh/xl/wh/wl once per chunk, 3 MMA combos)
// on the R9 multi-CTA shape: CTA 128x64, 4 warps, 2 stages x 48KB = 96KB
// -> 2 CTAs/SM. Traffic 768MB (vs 1.18GB 3-pass), barriers 16 (vs 48).

#define T_TOKENS 8192
#define DMODEL   1024
#define NSTATE   16

__device__ float          g_bc[T_TOKENS];
__device__ __nv_bfloat16  g_xh[T_TOKENS * DMODEL];
__device__ __nv_bfloat16  g_xl[T_TOKENS * DMODEL];
__device__ __nv_bfloat16  g_wh[DMODEL * DMODEL];
__device__ __nv_bfloat16  g_wl[DMODEL * DMODEL];

// ---------------------------------------------------------------------------
__device__ __forceinline__ uint32_t smem_u32(const void* p) {
    uint32_t a;
    asm("{ .reg .u64 t; cvta.to.shared.u64 t, %1; cvt.u32.u64 %0, t; }"
        : "=r"(a) : "l"(p));
    return a;
}

#define SW128(o) ((o) ^ (((o) >> 3) & 0x70))

#define CP_ASYNC16(dst, src) \
    asm volatile("cp.async.cg.shared.global [%0], [%1], 16;" \
                 :: "r"(dst), "l"(src) : "memory")
#define CP_COMMIT() asm volatile("cp.async.commit_group;" ::: "memory")
#define CP_WAIT0()  asm volatile("cp.async.wait_group 0;" ::: "memory")

#define LDSM4(r, addr) \
    asm volatile("ldmatrix.sync.aligned.m8n8.x4.shared.b16 {%0,%1,%2,%3}, [%4];" \
        : "=r"((r)[0]), "=r"((r)[1]), "=r"((r)[2]), "=r"((r)[3]) : "r"(addr))

#define MMA16816(d, a, b0v, b1v) \
    asm volatile("mma.sync.aligned.m16n8k16.row.col.f32.bf16.bf16.f32 " \
        "{%0,%1,%2,%3}, {%4,%5,%6,%7}, {%8,%9}, {%0,%1,%2,%3};" \
        : "+f"((d)[0]), "+f"((d)[1]), "+f"((d)[2]), "+f"((d)[3]) \
        : "r"((a)[0]), "r"((a)[1]), "r"((a)[2]), "r"((a)[3]), \
          "r"(b0v), "r"(b1v))

__device__ __forceinline__ float softplus_f(float z) {
    return fmaxf(z, 0.f) + __logf(1.f + __expf(-fabsf(z)));
}

// ---------------------------------------------------------------------------
// Kernel A: fp32 -> (bf16 hi, bf16 lo) split (W1 only; x-split fused in B).
// ---------------------------------------------------------------------------
__global__ __launch_bounds__(256) void split_kernel(
    const float* __restrict__ src, __nv_bfloat16* __restrict__ hi,
    __nv_bfloat16* __restrict__ lo, int n4)
{
    int i = blockIdx.x * blockDim.x + threadIdx.x;
    if (i >= n4) return;
    float4 v = reinterpret_cast<const float4*>(src)[i];
    float f[4] = {v.x, v.y, v.z, v.w};
    __nv_bfloat16 h[4], l[4];
    #pragma unroll
    for (int j = 0; j < 4; j++) {
        h[j] = __float2bfloat16(f[j]);
        l[j] = __float2bfloat16(f[j] - __bfloat162float(h[j]));
    }
    ushort4 ho, lov;
    ho.x = *(unsigned short*)&h[0]; ho.y = *(unsigned short*)&h[1];
    ho.z = *(unsigned short*)&h[2]; ho.w = *(unsigned short*)&h[3];
    lov.x = *(unsigned short*)&l[0]; lov.y = *(unsigned short*)&l[1];
    lov.z = *(unsigned short*)&l[2]; lov.w = *(unsigned short*)&l[3];
    reinterpret_cast<ushort4*>(hi)[i] = ho;
    reinterpret_cast<ushort4*>(lo)[i] = lov;
}

// ---------------------------------------------------------------------------
// Kernel B: bc[t] = sum_n (x[t]·W2[n]+b2[n])*(x[t]·W3[n]+b3[n]); also emits
// the bf16 hi/lo split of x. 32 tokens/block, grid 256 (>148 SMs).
// ---------------------------------------------------------------------------
__global__ __launch_bounds__(256) void bc_split_kernel(
    const float* __restrict__ x,
    const float* __restrict__ W2, const float* __restrict__ b2,
    const float* __restrict__ W3, const float* __restrict__ b3)
{
    const int TPB = 32, KC = 32;
    __shared__ float xs[TPB][36];
    __shared__ float w2s[NSTATE][36];
    __shared__ float w3s[NSTATE][36];
    __shared__ float red[TPB][17];

    int tid = threadIdx.x;
    int n   = tid & 15;
    int gid = tid >> 4;               // 0..15, 2 tokens each
    int rowBase = blockIdx.x * TPB;

    float accB[2] = {0.f, 0.f};
    float accC[2] = {0.f, 0.f};

    for (int k0 = 0; k0 < DMODEL; k0 += KC) {
        {   // x chunk: 32 rows x 32 k = 256 float4, 1 per thread
            int row = tid >> 3, q = tid & 7;
            size_t gofs = (size_t)(rowBase + row) * DMODEL + k0 + q * 4;
            float4 v = *reinterpret_cast<const float4*>(x + gofs);
            xs[row][q*4+0] = v.x; xs[row][q*4+1] = v.y;
            xs[row][q*4+2] = v.z; xs[row][q*4+3] = v.w;
            float f4[4] = {v.x, v.y, v.z, v.w};
            __nv_bfloat16 h[4], l[4];
            #pragma unroll
            for (int e = 0; e < 4; e++) {
                h[e] = __float2bfloat16(f4[e]);
                l[e] = __float2bfloat16(f4[e] - __bfloat162float(h[e]));
            }
            ushort4 ho, lov;
            ho.x = *(unsigned short*)&h[0]; ho.y = *(unsigned short*)&h[1];
            ho.z = *(unsigned short*)&h[2]; ho.w = *(unsigned short*)&h[3];
            lov.x = *(unsigned short*)&l[0]; lov.y = *(unsigned short*)&l[1];
            lov.z = *(unsigned short*)&l[2]; lov.w = *(unsigned short*)&l[3];
            *reinterpret_cast<ushort4*>(g_xh + gofs) = ho;
            *reinterpret_cast<ushort4*>(g_xl + gofs) = lov;
        }
        {   // W2/W3 chunk: 16 x 32 each = 128 float4 each
            int f = tid & 127, row = f >> 3, q = f & 7;
            const float* src = (tid < 128) ? W2 : W3;
            float4 v = *reinterpret_cast<const float4*>(
                src + (size_t)row * DMODEL + k0 + q * 4);
            float (*dst)[36] = (tid < 128) ? w2s : w3s;
            dst[row][q*4+0] = v.x; dst[row][q*4+1] = v.y;
            dst[row][q*4+2] = v.z; dst[row][q*4+3] = v.w;
        }
        __syncthreads();

        #pragma unroll 8
        for (int kk = 0; kk < KC; kk++) {
            float w2 = w2s[n][kk], w3 = w3s[n][kk];
            #pragma unroll
            for (int t = 0; t < 2; t++) {
                float xv = xs[gid*2 + t][kk];
                accB[t] = fmaf(xv, w2, accB[t]);
                accC[t] = fmaf(xv, w3, accC[t]);
            }
        }
        __syncthreads();
    }

    float bb = b2[n], bb3 = b3[n];
    #pragma unroll
    for (int t = 0; t < 2; t++)
        red[gid*2 + t][n] = (accB[t] + bb) * (accC[t] + bb3);
    __syncthreads();

    if (tid < TPB) {
        float s = 0.f;
        #pragma unroll
        for (int nn = 0; nn < NSTATE; nn++) s += red[tid][nn];
        g_bc[rowBase + tid] = s;
    }
}

// ---------------------------------------------------------------------------
// Kernel C: merged-pass mma.sync bf16 GEMM + fused epilogue.
// CTA 128(M) x 64(N), 128 threads = 4 warps, warp tile 64x32.
// 16 K-chunks of 64; per chunk load AH/AL/BH/BL once, 3 MMA combos.
// 2-stage cp.async pipeline (48KB/stage, 96KB total) -> 2 CTAs/SM.
// ---------------------------------------------------------------------------
#define NCHUNKS 16
#define A_SUB   16384                       // 128 rows x 128B
#define B_SUB   8192                        // 64 rows x 128B
#define STAGE_B (2 * A_SUB + 2 * B_SUB)     // 48 KB
#define SMEM_TOTAL (2 * STAGE_B)            // 96 KB

__global__ __launch_bounds__(128) void mma_kernel(
    const float* __restrict__ x,
    const float* __restrict__ b1,
    float* __restrict__ y)
{
    extern __shared__ char smem[];
    const uint32_t sbase = smem_u32(smem);
    const int tid  = threadIdx.x;
    const int wid  = tid >> 5;
    const int lane = tid & 31;

    const int rowBase = blockIdx.y * 128;
    const int colBase = blockIdx.x * 64;

    const int wm = wid & 1;           // M half (64 rows)
    const int wn = wid >> 1;          // N half (32 cols)

    const __nv_bfloat16* pAH = g_xh + (size_t)rowBase * DMODEL;
    const __nv_bfloat16* pAL = g_xl + (size_t)rowBase * DMODEL;
    const __nv_bfloat16* pBH = g_wh + (size_t)colBase * DMODEL;
    const __nv_bfloat16* pBL = g_wl + (size_t)colBase * DMODEL;

    // ldmatrix per-lane coords (validated fragment algebra)
    const int a_row  = (lane & 7) + ((lane >> 3) & 1) * 8;       // 0..15
    const int a_byte = (lane >> 4) * 16;                          // k-half
    const int axor   = (a_row & 7) << 4;
    const int b_row  = ((lane >> 4) & 1) * 8 + (lane & 7);        // n within 16
    const int b_byte = ((lane >> 3) & 1) * 16;                    // k-half
    const int bxor   = (b_row & 7) << 4;

    float acc[4][4][4];
    #pragma unroll
    for (int mi = 0; mi < 4; mi++)
        #pragma unroll
        for (int ni = 0; ni < 4; ni++)
            #pragma unroll
            for (int r = 0; r < 4; r++) acc[mi][ni][r] = 0.f;

    // cp.async coords (128 threads): row = tid>>3 (0..15), q = tid&7
    const int cp_row = tid >> 3;
    const int cp_q   = tid & 7;

    // per-chunk loader: A subtiles 8 rows-groups, B subtiles 4
    #define LOAD_CHUNK(stage, kc)                                             \
    do {                                                                      \
        uint32_t st_ = sbase + (uint32_t)(stage) * STAGE_B;                   \
        uint32_t AH_ = st_, AL_ = st_ + A_SUB;                                \
        uint32_t BH_ = st_ + 2 * A_SUB, BL_ = BH_ + B_SUB;                    \
        _Pragma("unroll")                                                     \
        for (int u = 0; u < 8; u++) {                                         \
            int row = cp_row + u * 16;                                        \
            uint32_t so = SW128(row * 128 + cp_q * 16);                       \
            size_t go = (size_t)row * DMODEL + (kc) + cp_q * 8;               \
            CP_ASYNC16(AH_ + so, pAH + go);                                   \
            CP_ASYNC16(AL_ + so, pAL + go);                                   \
        }                                                                     \
        _Pragma("unroll")                                                     \
        for (int u = 0; u < 4; u++) {                                         \
            int row = cp_row + u * 16;                                        \
            uint32_t so = SW128(row * 128 + cp_q * 16);                       \
            size_t go = (size_t)row * DMODEL + (kc) + cp_q * 8;               \
            CP_ASYNC16(BH_ + so, pBH + go);                                   \
            CP_ASYNC16(BL_ + so, pBL + go);                                   \
        }                                                                     \
        CP_COMMIT();                                                          \
    } while (0)

    // prologue: issue chunk 0
    LOAD_CHUNK(0, 0);

    #pragma unroll 1
    for (int g = 0; g < NCHUNKS; g++) {
        CP_WAIT0();
        __syncthreads();

        // issue chunk g+1 into the other stage (overlaps compute below)
        if (g + 1 < NCHUNKS) {
            LOAD_CHUNK((g + 1) & 1, (g + 1) << 6);
        }

        const uint32_t st = sbase + (uint32_t)(g & 1) * STAGE_B;
        const uint32_t AH = st;
        const uint32_t AL = st + A_SUB;
        const uint32_t BH = st + 2 * A_SUB;
        const uint32_t BL = BH + B_SUB;

        #pragma unroll
        for (int s = 0; s < 4; s++) {
            const int kb = s * 32;                 // 16 bf16 = 32B per kstep
            uint32_t ah[4][4], al[4][4], bh[2][4], bl[2][4];
            #pragma unroll
            for (int mi = 0; mi < 4; mi++) {
                uint32_t ro = (uint32_t)((wm * 64 + mi * 16 + a_row) * 128)
                            + (uint32_t)((kb + a_byte) ^ axor);
                LDSM4(ah[mi], AH + ro);
                LDSM4(al[mi], AL + ro);
            }
            #pragma unroll
            for (int bt = 0; bt < 2; bt++) {
                uint32_t ro = (uint32_t)((wn * 32 + bt * 16 + b_row) * 128)
                            + (uint32_t)((kb + b_byte) ^ bxor);
                LDSM4(bh[bt], BH + ro);
                LDSM4(bl[bt], BL + ro);
            }
            #pragma unroll
            for (int mi = 0; mi < 4; mi++) {
                #pragma unroll
                for (int ni = 0; ni < 4; ni++) {
                    const int bq = ni >> 1;
                    const int o  = (ni & 1) * 2;
                    MMA16816(acc[mi][ni], ah[mi], bh[bq][o], bh[bq][o + 1]);
                    MMA16816(acc[mi][ni], al[mi], bh[bq][o], bh[bq][o + 1]);
                    MMA16816(acc[mi][ni], ah[mi], bl[bq][o], bl[bq][o + 1]);
                }
            }
        }
    }
    #undef LOAD_CHUNK

    // Epilogue: y = x * softplus(z + b1) * bc
    const int gq = lane >> 2;    // row-in-8 group
    const int tq = lane & 3;     // col pair
    #pragma unroll
    for (int mi = 0; mi < 4; mi++) {
        int r0 = rowBase + wm * 64 + mi * 16 + gq;
        int r1 = r0 + 8;
        float bc0 = g_bc[r0], bc1 = g_bc[r1];
        const float* x0 = x + (size_t)r0 * DMODEL;
        const float* x1 = x + (size_t)r1 * DMODEL;
        float* y0 = y + (size_t)r0 * DMODEL;
        float* y1 = y + (size_t)r1 * DMODEL;
        #pragma unroll
        for (int ni = 0; ni < 4; ni++) {
            int c = colBase + wn * 32 + ni * 8 + tq * 2;
            float2 bv  = *reinterpret_cast<const float2*>(b1 + c);
            float2 xv0 = *reinterpret_cast<const float2*>(x0 + c);
            float2 xv1 = *reinterpret_cast<const float2*>(x1 + c);
            float2 o0, o1;
            o0.x = xv0.x * softplus_f(acc[mi][ni][0] + bv.x) * bc0;
            o0.y = xv0.y * softplus_f(acc[mi][ni][1] + bv.y) * bc0;
            o1.x = xv1.x * softplus_f(acc[mi][ni][2] + bv.x) * bc1;
            o1.y = xv1.y * softplus_f(acc[mi][ni][3] + bv.y) * bc1;
            *reinterpret_cast<float2*>(y0 + c) = o0;
            *reinterpret_cast<float2*>(y1 + c) = o1;
        }
    }
}

// ---------------------------------------------------------------------------
extern "C" void kernel_launch(void* const* d_in, const int* in_sizes, int n_in,
                              void* d_out, int out_size)
{
    const float* x  = (const float*)d_in[0];
    const float* W1 = (const float*)d_in[1];
    const float* b1 = (const float*)d_in[2];
    const float* W2 = (const float*)d_in[3];
    const float* b2 = (const float*)d_in[4];
    const float* W3 = (const float*)d_in[5];
    const float* b3 = (const float*)d_in[6];
    float* y = (float*)d_out;

    __nv_bfloat16 *wh, *wl;
    cudaGetSymbolAddress((void**)&wh, g_wh);
    cudaGetSymbolAddress((void**)&wl, g_wl);

    int nw4 = DMODEL * DMODEL / 4;
    split_kernel<<<nw4 / 256, 256>>>(W1, wh, wl, nw4);
    bc_split_kernel<<<T_TOKENS / 32, 256>>>(x, W2, b2, W3, b3);

    cudaFuncSetAttribute(mma_kernel, cudaFuncAttributeMaxDynamicSharedMemorySize,
                         SMEM_TOTAL);
    mma_kernel<<<dim3(DMODEL / 64, T_TOKENS / 128), 128, SMEM_TOTAL>>>(x, b1, y);
}